// round 10
// baseline (speedup 1.0000x reference)
#include <cuda_runtime.h>
#include <cstdint>
#include <math.h>

// Problem constants
#define LAYERS 63
#define BATCH  2048
#define BT     32          // batch elements per tile
#define TILES  4           // tiles per CTA
#define NTHREADS 512
#define ROWS   (BT * 12)   // 384

// ---------------- shared memory layout (floats) ----------------
#define S_W1    0          // 192
#define S_FB1   192        // 64
#define S_FB2   256        // 64
#define S_FW3   320        // 64
#define S_FB3   384        // 1 (pad to 400)
#define S_ZS0   400        // 768
#define S_ZS1   1168       // 768 -> 1936 (pad 1952)
#define S_H1    1952       // 384*36 = 13824 -> 15776
#define S_G     15776      // 384*68 = 26112 -> 41888
#define S_W2P   41888      // fragment-permuted W2 (tf32): 12*2*32*8 = 6144 -> 48032
#define SMEM_FLOATS 48032
#define SMEM_BYTES (SMEM_FLOATS * 4)   // 192,128 B

// aliases into dead regions
#define S_POOL  S_H1               // 32*132 = 4224 (h1 dead after GEMM)
#define S_FW1   (S_H1 + 4224)      // 8192 -> ends 14368 <= 15776 (incl pad)
#define S_H2    S_G                // h2[384][68]
#define S_FW2   S_G                // 4096 (h2 dead after pool)
#define S_F1    (S_G + 4096)       // 32*68 = 2176
#define S_F2    (S_G + 6272)       // 2176 -> 8448 <= 26112

// ---------------- helpers ----------------
__device__ __forceinline__ float to_tf32(float x) {
    uint32_t u;
    asm("cvt.rna.tf32.f32 %0, %1;" : "=r"(u) : "f"(x));
    return __uint_as_float(u);
}
__device__ __forceinline__ void mma_tf32(float* c,
                                         uint32_t a0, uint32_t a1, uint32_t a2, uint32_t a3,
                                         uint32_t b0, uint32_t b1) {
    asm volatile(
        "mma.sync.aligned.m16n8k8.row.col.f32.tf32.tf32.f32 "
        "{%0,%1,%2,%3}, {%4,%5,%6,%7}, {%8,%9}, {%0,%1,%2,%3};"
        : "+f"(c[0]), "+f"(c[1]), "+f"(c[2]), "+f"(c[3])
        : "r"(a0), "r"(a1), "r"(a2), "r"(a3), "r"(b0), "r"(b1));
}
__device__ __forceinline__ void ldsm4(uint32_t& a0, uint32_t& a1,
                                      uint32_t& a2, uint32_t& a3, uint32_t addr) {
    asm volatile("ldmatrix.sync.aligned.m8n8.x4.shared.b16 {%0,%1,%2,%3}, [%4];"
                 : "=r"(a0), "=r"(a1), "=r"(a2), "=r"(a3) : "r"(addr));
}
__device__ __forceinline__ void fma2(unsigned long long& d,
                                     unsigned long long a,
                                     unsigned long long b) {
    asm("fma.rn.f32x2 %0, %1, %2, %0;" : "+l"(d) : "l"(a), "l"(b));
}
__device__ __forceinline__ unsigned long long pk(float a) {
    unsigned long long r;
    asm("mov.b64 %0, {%1, %1};" : "=l"(r) : "f"(a));
    return r;
}
__device__ __forceinline__ unsigned long long pk2(float lo, float hi) {
    unsigned long long r;
    asm("mov.b64 %0, {%1, %2};" : "=l"(r) : "f"(lo), "f"(hi));
    return r;
}
__device__ __forceinline__ void unpk(unsigned long long v, float& lo, float& hi) {
    asm("mov.b64 {%0, %1}, %2;" : "=f"(lo), "=f"(hi) : "l"(v));
}

__global__ void __launch_bounds__(NTHREADS, 1)
twelve_sites_kernel(const float* __restrict__ zs,
                    const float* __restrict__ w1,
                    const float* __restrict__ w2,
                    const float* __restrict__ fw1,
                    const float* __restrict__ fb1,
                    const float* __restrict__ fw2,
                    const float* __restrict__ fb2,
                    const float* __restrict__ fw3,
                    const float* __restrict__ fb3,
                    float* __restrict__ out)
{
    extern __shared__ float sm[];
    const int l   = blockIdx.y;
    const int bg  = blockIdx.x;
    const int b0g = bg * (BT * TILES);
    const int tid = threadIdx.x;
    const int wid = tid >> 5;
    const int lid = tid & 31;
    const uint32_t smu = (uint32_t)__cvta_generic_to_shared(sm);

    // ---------------- prologue ----------------
    for (int i = tid; i < 192; i += NTHREADS) sm[S_W1 + i] = w1[l * 192 + i];
    if (tid < 64) {
        sm[S_FB1 + tid] = fb1[l * 64 + tid];
        sm[S_FB2 + tid] = fb2[l * 64 + tid];
        sm[S_FW3 + tid] = fw3[l * 64 + tid];
    }
    if (tid == 0) sm[S_FB3] = fb3[l];
    // W2 -> fragment-permuted table: entry ((ks*2+nbh)*32+lane)*8 + j
    //   j in 0..3: b0[nt=j]  (k = ks*8+tg),  j in 4..7: b1[nt=j-4] (k = ks*8+tg+4)
    //   n = nbh*32 + nt*8 + gid, where gid = lane>>2, tg = lane&3
    for (int i = tid; i < 6144; i += NTHREADS) {
        int j    = i & 7;
        int lane = (i >> 3) & 31;
        int nbh  = (i >> 8) & 1;
        int ks   = i >> 9;
        int gid  = lane >> 2, tg = lane & 3;
        int nt   = j & 3;
        int k    = ks * 8 + tg + (j >> 2) * 4;
        int n    = nbh * 32 + nt * 8 + gid;
        sm[S_W2P + i] = to_tf32(w2[(size_t)l * 6144 + k * 64 + n]);
    }
    // zs tile 0
    if (tid < 192) {
        int i = tid / 6, j = tid % 6;
        *(float4*)(sm + S_ZS0 + i * 24 + j * 4) =
            *(const float4*)(zs + ((size_t)(b0g + i) * LAYERS + l) * 24 + j * 4);
    }
    __syncthreads();

    const float4* fw1v = (const float4*)(fw1 + (size_t)l * 8192);
    const float4* fw2v = (const float4*)(fw2 + (size_t)l * 4096);

    for (int t = 0; t < TILES; t++) {
        const int b0 = b0g + t * BT;
        const float* zbuf = sm + ((t & 1) ? S_ZS1 : S_ZS0);
        float* zbuf_next  = sm + ((t & 1) ? S_ZS0 : S_ZS1);

        // prefetch next zs tile
        float4 zreg;
        const bool zpre = (t + 1 < TILES) && (tid < 192);
        if (zpre) {
            int i = tid / 6, j = tid % 6;
            zreg = *(const float4*)(zs + ((size_t)(b0 + BT + i) * LAYERS + l) * 24 + j * 4);
        }

        // ---------------- Phase A: CNN1 -> h1[384][36] (tf32-rounded) ----------------
        if (tid < ROWS) {
            const int r  = tid;
            const int bt = r / 12;
            const int s  = r % 12;
            const float* xz = zbuf + bt * 24;
            const int sp1 = (s + 1) % 12, sm1 = (s + 11) % 12;
            const int sp2 = (s + 2) % 12, sm2 = (s + 10) % 12;
            const int sp3 = (s + 3) % 12, sm3 = (s + 9) % 12;
            const int sp4 = (s + 4) % 12, sm4 = (s + 8) % 12;
            float a0 = xz[s * 2 + 0];
            float a1 = xz[s * 2 + 1];
            float a2 = xz[sp1*2]   + xz[sm1*2]   + xz[sp3*2]   + xz[sm3*2];
            float a3 = xz[sp1*2+1] + xz[sm1*2+1] + xz[sp3*2+1] + xz[sm3*2+1];
            float a4 = xz[sp2*2]   + xz[sm2*2]   + xz[sp4*2]   + xz[sm4*2];
            float a5 = xz[sp2*2+1] + xz[sm2*2+1] + xz[sp4*2+1] + xz[sm4*2+1];
            float* hrow = sm + S_H1 + r * 36;
            const float4* W4 = (const float4*)(sm + S_W1);
            #pragma unroll
            for (int c4 = 0; c4 < 8; c4++) {
                float4 q0 = W4[c4],      q1 = W4[8 + c4],  q2 = W4[16 + c4];
                float4 q3 = W4[24 + c4], q4 = W4[32 + c4], q5 = W4[40 + c4];
                float4 v;
                v.x = to_tf32(fmaxf(a0*q0.x + a1*q1.x + a2*q2.x + a3*q3.x + a4*q4.x + a5*q5.x, 0.f));
                v.y = to_tf32(fmaxf(a0*q0.y + a1*q1.y + a2*q2.y + a3*q3.y + a4*q4.y + a5*q5.y, 0.f));
                v.z = to_tf32(fmaxf(a0*q0.z + a1*q1.z + a2*q2.z + a3*q3.z + a4*q4.z + a5*q5.z, 0.f));
                v.w = to_tf32(fmaxf(a0*q0.w + a1*q1.w + a2*q2.w + a3*q3.w + a4*q4.w + a5*q5.w, 0.f));
                *(float4*)(hrow + c4 * 4) = v;
            }
        }
        __syncthreads();   // (1)

        // ---------------- Phase A2: g[384][68] (12-load scheme) ----------------
        if (tid < 256) {
            const int bt = tid >> 3;
            const int j4 = tid & 7;
            const float* hb = sm + S_H1 + bt * 12 * 36 + j4 * 4;
            float4 h[12];
            #pragma unroll
            for (int s = 0; s < 12; s++)
                h[s] = *(const float4*)(hb + s * 36);
            float* gb = sm + S_G + bt * 12 * 68 + j4 * 4;
            #pragma unroll
            for (int s = 0; s < 12; s++) {
                float4 p1 = h[(s+1)%12], m1 = h[(s+11)%12], p3 = h[(s+3)%12], m3 = h[(s+9)%12];
                float4 p2 = h[(s+2)%12], m2 = h[(s+10)%12], p4 = h[(s+4)%12], m4 = h[(s+8)%12];
                float4 g1, g2;
                g1.x = to_tf32(p1.x + m1.x + p3.x + m3.x);
                g1.y = to_tf32(p1.y + m1.y + p3.y + m3.y);
                g1.z = to_tf32(p1.z + m1.z + p3.z + m3.z);
                g1.w = to_tf32(p1.w + m1.w + p3.w + m3.w);
                g2.x = to_tf32(p2.x + m2.x + p4.x + m4.x);
                g2.y = to_tf32(p2.y + m2.y + p4.y + m4.y);
                g2.z = to_tf32(p2.z + m2.z + p4.z + m4.z);
                g2.w = to_tf32(p2.w + m2.w + p4.w + m4.w);
                *(float4*)(gb + s * 68)      = g1;
                *(float4*)(gb + s * 68 + 32) = g2;
            }
        }
        if (zpre) {
            int i = tid / 6, j = tid % 6;
            *(float4*)(zbuf_next + i * 24 + j * 4) = zreg;
        }
        __syncthreads();   // (2)

        // ---------------- Phase B: tf32 mma.sync GEMM (ldmatrix A, permuted B) ----------------
        float4 w1r[4];
        float4 w2r[2];
        {
            const int mrow = (wid >> 1) * 48;
            const int nbh  = wid & 1;
            const int gid  = lid >> 2;
            const int tg   = lid & 3;

            // ldmatrix per-lane source rows: row = lane&15, +16B for lanes>=16
            const int rowsel = lid & 15;
            const uint32_t hoff = (uint32_t)(lid >> 4) * 16u;
            uint32_t aH[3], aG[3];
            #pragma unroll
            for (int mt = 0; mt < 3; mt++) {
                const int r = mrow + mt * 16 + rowsel;
                aH[mt] = smu + (uint32_t)(S_H1 + r * 36) * 4u + hoff;
                aG[mt] = smu + (uint32_t)(S_G  + r * 68) * 4u + hoff;
            }
            const uint4* bp = (const uint4*)(sm + S_W2P + nbh * 256 + lid * 8);

            float acc[3][4][4];
            #pragma unroll
            for (int mt = 0; mt < 3; mt++)
                #pragma unroll
                for (int nt = 0; nt < 4; nt++)
                    #pragma unroll
                    for (int q = 0; q < 4; q++) acc[mt][nt][q] = 0.f;

            #pragma unroll
            for (int ks = 0; ks < 12; ks++) {
                uint4 b0v = bp[ks * 128];       // (ks*2+nbh)*32*8 floats = ks*128 uint4
                uint4 b1v = bp[ks * 128 + 1];
                uint32_t b0[4] = {b0v.x, b0v.y, b0v.z, b0v.w};
                uint32_t b1[4] = {b1v.x, b1v.y, b1v.z, b1v.w};
                #pragma unroll
                for (int mt = 0; mt < 3; mt++) {
                    uint32_t a0, a1, a2, a3;
                    uint32_t addr = (ks < 4) ? (aH[mt] + (uint32_t)ks * 32u)
                                             : (aG[mt] + (uint32_t)(ks - 4) * 32u);
                    ldsm4(a0, a1, a2, a3, addr);
                    #pragma unroll
                    for (int nt = 0; nt < 4; nt++)
                        mma_tf32(acc[mt][nt], a0, a1, a2, a3, b0[nt], b1[nt]);
                }
            }
            __syncthreads();   // (3) all reads of h1/g complete

            // store h2 (relu) into g region
            const int nb = nbh * 32;
            #pragma unroll
            for (int mt = 0; mt < 3; mt++) {
                const int r0 = mrow + mt * 16 + gid;
                #pragma unroll
                for (int nt = 0; nt < 4; nt++) {
                    const int cc = nb + nt * 8 + tg * 2;
                    float2 v0, v1;
                    v0.x = fmaxf(acc[mt][nt][0], 0.f);
                    v0.y = fmaxf(acc[mt][nt][1], 0.f);
                    v1.x = fmaxf(acc[mt][nt][2], 0.f);
                    v1.y = fmaxf(acc[mt][nt][3], 0.f);
                    *(float2*)(sm + S_H2 + r0 * 68 + cc)       = v0;
                    *(float2*)(sm + S_H2 + (r0 + 8) * 68 + cc) = v1;
                }
            }
        }

        // FW1/FW2 global prefetch (acc regs dead; latency hidden by pool)
        #pragma unroll
        for (int j = 0; j < 4; j++) w1r[j] = fw1v[tid + j * NTHREADS];
        #pragma unroll
        for (int j = 0; j < 2; j++) w2r[j] = fw2v[tid + j * NTHREADS];

        __syncthreads();   // (4) h2 visible, h1 fully dead

        // FW1 -> smem (h1 region, after pool area)
        #pragma unroll
        for (int j = 0; j < 4; j++)
            *(float4*)(sm + S_FW1 + (tid + j * NTHREADS) * 4) = w1r[j];

        // ---------------- Pool (vectorized): pooled[32][132] ----------------
        {
            const int bt = tid >> 4;     // 0..31
            const int o4 = tid & 15;     // column quad
            const float* q = sm + S_H2 + bt * 12 * 68 + o4 * 4;
            float4 v = *(const float4*)(q);
            float4 sum = v, mx = v;
            #pragma unroll
            for (int s = 1; s < 12; s++) {
                float4 u = *(const float4*)(q + s * 68);
                sum.x += u.x; sum.y += u.y; sum.z += u.z; sum.w += u.w;
                mx.x = fmaxf(mx.x, u.x); mx.y = fmaxf(mx.y, u.y);
                mx.z = fmaxf(mx.z, u.z); mx.w = fmaxf(mx.w, u.w);
            }
            sum.x *= (1.0f / 12.0f); sum.y *= (1.0f / 12.0f);
            sum.z *= (1.0f / 12.0f); sum.w *= (1.0f / 12.0f);
            *(float4*)(sm + S_POOL + bt * 132 + o4 * 4)      = sum;
            *(float4*)(sm + S_POOL + bt * 132 + 64 + o4 * 4) = mx;
        }
        __syncthreads();   // (5) h2 dead

        // FW2 -> smem (h2/G region)
        #pragma unroll
        for (int j = 0; j < 2; j++)
            *(float4*)(sm + S_FW2 + (tid + j * NTHREADS) * 4) = w2r[j];

        // ---------------- fc1 (128->64) + relu. warp = oq, lane = bt ----------------
        {
            const int bt = lid;
            const int oq = wid;
            float4 b4 = *(const float4*)(sm + S_FB1 + oq * 4);
            unsigned long long acc0 = pk2(b4.x, b4.y);
            unsigned long long acc1 = pk2(b4.z, b4.w);
            const float4* pool4 = (const float4*)(sm + S_POOL + bt * 132);
            #pragma unroll 8
            for (int f4 = 0; f4 < 32; f4++) {
                float4 p4 = pool4[f4];
                #pragma unroll
                for (int kk = 0; kk < 4; kk++) {
                    ulonglong2 w = *(const ulonglong2*)(sm + S_FW1 + (f4 * 4 + kk) * 64 + oq * 4);
                    unsigned long long aa = pk((&p4.x)[kk]);
                    fma2(acc0, aa, w.x);
                    fma2(acc1, aa, w.y);
                }
            }
            float v0, v1, v2, v3;
            unpk(acc0, v0, v1);
            unpk(acc1, v2, v3);
            float4 v;
            v.x = fmaxf(v0, 0.f); v.y = fmaxf(v1, 0.f);
            v.z = fmaxf(v2, 0.f); v.w = fmaxf(v3, 0.f);
            *(float4*)(sm + S_F1 + bt * 68 + oq * 4) = v;
        }
        __syncthreads();   // (6)

        // ---------------- fc2 (64->64) + relu ----------------
        {
            const int bt = lid;
            const int oq = wid;
            float4 b4 = *(const float4*)(sm + S_FB2 + oq * 4);
            unsigned long long acc0 = pk2(b4.x, b4.y);
            unsigned long long acc1 = pk2(b4.z, b4.w);
            const float4* f1r = (const float4*)(sm + S_F1 + bt * 68);
            #pragma unroll 8
            for (int k4 = 0; k4 < 16; k4++) {
                float4 p4 = f1r[k4];
                #pragma unroll
                for (int kk = 0; kk < 4; kk++) {
                    ulonglong2 w = *(const ulonglong2*)(sm + S_FW2 + (k4 * 4 + kk) * 64 + oq * 4);
                    unsigned long long aa = pk((&p4.x)[kk]);
                    fma2(acc0, aa, w.x);
                    fma2(acc1, aa, w.y);
                }
            }
            float v0, v1, v2, v3;
            unpk(acc0, v0, v1);
            unpk(acc1, v2, v3);
            float4 v;
            v.x = fmaxf(v0, 0.f); v.y = fmaxf(v1, 0.f);
            v.z = fmaxf(v2, 0.f); v.w = fmaxf(v3, 0.f);
            *(float4*)(sm + S_F2 + bt * 68 + oq * 4) = v;
        }
        __syncthreads();   // (7)

        // ---------------- fc3 (64->1) -> out (B, L) ----------------
        if (tid < BT) {
            const float4* f2 = (const float4*)(sm + S_F2 + tid * 68);
            const float4* w3 = (const float4*)(sm + S_FW3);
            float acc = sm[S_FB3];
            #pragma unroll
            for (int k4 = 0; k4 < 16; k4++) {
                float4 a = f2[k4], b = w3[k4];
                acc += a.x * b.x + a.y * b.y + a.z * b.z + a.w * b.w;
            }
            out[(size_t)(b0 + tid) * LAYERS + l] = acc;
        }
        // next phase A writes h1 (pool/FW1 dead after fc1 sync (6));
        // A2 writes G (FW2/F1/F2 dead after fc2/fc3, all threads passed (7)).
    }
}

extern "C" void kernel_launch(void* const* d_in, const int* in_sizes, int n_in,
                              void* d_out, int out_size)
{
    (void)in_sizes; (void)n_in; (void)out_size;
    const float* zs  = (const float*)d_in[0];
    const float* w1  = (const float*)d_in[1];
    const float* w2  = (const float*)d_in[2];
    const float* fw1 = (const float*)d_in[3];
    const float* fb1 = (const float*)d_in[4];
    const float* fw2 = (const float*)d_in[5];
    const float* fb2 = (const float*)d_in[6];
    const float* fw3 = (const float*)d_in[7];
    const float* fb3 = (const float*)d_in[8];
    float* out = (float*)d_out;

    static bool attr_set = false;
    if (!attr_set) {
        cudaFuncSetAttribute(twelve_sites_kernel,
                             cudaFuncAttributeMaxDynamicSharedMemorySize,
                             SMEM_BYTES);
        attr_set = true;
    }

    dim3 grid(BATCH / (BT * TILES), LAYERS);   // (16, 63)
    twelve_sites_kernel<<<grid, NTHREADS, SMEM_BYTES>>>(
        zs, w1, w2, fw1, fb1, fw2, fb2, fw3, fb3, out);
}

// round 15
// speedup vs baseline: 1.0667x; 1.0667x over previous
#include <cuda_runtime.h>
#include <cstdint>
#include <math.h>

// Problem constants
#define LAYERS 63
#define BATCH  2048
#define BT     16          // batch elements per tile
#define TILES  8           // tiles per CTA
#define NTHREADS 256
#define ROWS   (BT * 12)   // 192

// ---------------- shared memory layout (floats) ----------------
#define S_W1    0          // 192
#define S_FB1   192        // 64
#define S_FB2   256        // 64
#define S_FW3   320        // 64
#define S_FB3   384        // 1 (pad to 400)
#define S_ZS0   400        // 16*24 = 384
#define S_ZS1   784        // 384 -> 1168 (pad 1184)
#define S_H1    1184       // 192*36 = 6912 -> 8096
#define S_G     8096       // 192*68 = 13056 -> 21152
#define S_W2    21152      // 96*72 = 6912 -> 28064 (tf32, stride 72)
#define SMEM_FLOATS 28064
#define SMEM_BYTES (SMEM_FLOATS * 4)   // 112,256 B -> 2 CTAs/SM

// aliases into dead regions
#define S_POOL  S_H1               // 16*132 = 2112 (h1 dead after GEMM)
#define S_FW2   (S_H1 + 2112)      // 4096 -> 6208 <= 6912
#define S_H2    S_G                // h2[192][68]
#define S_FW1   S_G                // 8192 (h2 dead after pool)
#define S_F1    (S_G + 8192)       // 16*68 = 1088
#define S_F2    (S_G + 9280)       // 1088 -> 10368 <= 13056

// ---------------- helpers ----------------
__device__ __forceinline__ float to_tf32(float x) {
    uint32_t u;
    asm("cvt.rna.tf32.f32 %0, %1;" : "=r"(u) : "f"(x));
    return __uint_as_float(u);
}
__device__ __forceinline__ void mma_tf32(float* c,
                                         uint32_t a0, uint32_t a1, uint32_t a2, uint32_t a3,
                                         uint32_t b0, uint32_t b1) {
    asm volatile(
        "mma.sync.aligned.m16n8k8.row.col.f32.tf32.tf32.f32 "
        "{%0,%1,%2,%3}, {%4,%5,%6,%7}, {%8,%9}, {%0,%1,%2,%3};"
        : "+f"(c[0]), "+f"(c[1]), "+f"(c[2]), "+f"(c[3])
        : "r"(a0), "r"(a1), "r"(a2), "r"(a3), "r"(b0), "r"(b1));
}
__device__ __forceinline__ void fma2(unsigned long long& d,
                                     unsigned long long a,
                                     unsigned long long b) {
    asm("fma.rn.f32x2 %0, %1, %2, %0;" : "+l"(d) : "l"(a), "l"(b));
}
__device__ __forceinline__ unsigned long long pk(float a) {
    unsigned long long r;
    asm("mov.b64 %0, {%1, %1};" : "=l"(r) : "f"(a));
    return r;
}
__device__ __forceinline__ unsigned long long pk2(float lo, float hi) {
    unsigned long long r;
    asm("mov.b64 %0, {%1, %2};" : "=l"(r) : "f"(lo), "f"(hi));
    return r;
}
__device__ __forceinline__ void unpk(unsigned long long v, float& lo, float& hi) {
    asm("mov.b64 {%0, %1}, %2;" : "=f"(lo), "=f"(hi) : "l"(v));
}

__global__ void __launch_bounds__(NTHREADS, 2)
twelve_sites_kernel(const float* __restrict__ zs,
                    const float* __restrict__ w1,
                    const float* __restrict__ w2,
                    const float* __restrict__ fw1,
                    const float* __restrict__ fb1,
                    const float* __restrict__ fw2,
                    const float* __restrict__ fb2,
                    const float* __restrict__ fw3,
                    const float* __restrict__ fb3,
                    float* __restrict__ out)
{
    extern __shared__ float sm[];
    const int l   = blockIdx.y;
    const int bg  = blockIdx.x;
    const int b0g = bg * (BT * TILES);
    const int tid = threadIdx.x;
    const int wid = tid >> 5;
    const int lid = tid & 31;

    // ---------------- prologue ----------------
    for (int i = tid; i < 192; i += NTHREADS) sm[S_W1 + i] = w1[l * 192 + i];
    if (tid < 64) {
        sm[S_FB1 + tid] = fb1[l * 64 + tid];
        sm[S_FB2 + tid] = fb2[l * 64 + tid];
        sm[S_FW3 + tid] = fw3[l * 64 + tid];
    }
    if (tid == 0) sm[S_FB3] = fb3[l];
    // W2 (k-major [96][64]) -> smem stride 72, tf32-rounded
    for (int i = tid; i < 6144; i += NTHREADS) {
        int k = i >> 6, n = i & 63;
        sm[S_W2 + k * 72 + n] = to_tf32(w2[(size_t)l * 6144 + i]);
    }
    // zs tile 0
    if (tid < 96) {
        int i = tid / 6, j = tid % 6;
        *(float4*)(sm + S_ZS0 + i * 24 + j * 4) =
            *(const float4*)(zs + ((size_t)(b0g + i) * LAYERS + l) * 24 + j * 4);
    }
    __syncthreads();

    const float4* fw1v = (const float4*)(fw1 + (size_t)l * 8192);
    const float4* fw2v = (const float4*)(fw2 + (size_t)l * 4096);

    for (int t = 0; t < TILES; t++) {
        const int b0 = b0g + t * BT;
        const float* zbuf = sm + ((t & 1) ? S_ZS1 : S_ZS0);
        float* zbuf_next  = sm + ((t & 1) ? S_ZS0 : S_ZS1);

        // prefetch next zs tile
        float4 zreg;
        const bool zpre = (t + 1 < TILES) && (tid < 96);
        if (zpre) {
            int i = tid / 6, j = tid % 6;
            zreg = *(const float4*)(zs + ((size_t)(b0 + BT + i) * LAYERS + l) * 24 + j * 4);
        }

        // ---------------- Phase A: CNN1 -> h1[192][36] (tf32-rounded) ----------------
        if (tid < ROWS) {
            const int r  = tid;
            const int bt = r / 12;
            const int s  = r % 12;
            const float* xz = zbuf + bt * 24;
            const int sp1 = (s + 1) % 12, sm1 = (s + 11) % 12;
            const int sp2 = (s + 2) % 12, sm2 = (s + 10) % 12;
            const int sp3 = (s + 3) % 12, sm3 = (s + 9) % 12;
            const int sp4 = (s + 4) % 12, sm4 = (s + 8) % 12;
            float a0 = xz[s * 2 + 0];
            float a1 = xz[s * 2 + 1];
            float a2 = xz[sp1*2]   + xz[sm1*2]   + xz[sp3*2]   + xz[sm3*2];
            float a3 = xz[sp1*2+1] + xz[sm1*2+1] + xz[sp3*2+1] + xz[sm3*2+1];
            float a4 = xz[sp2*2]   + xz[sm2*2]   + xz[sp4*2]   + xz[sm4*2];
            float a5 = xz[sp2*2+1] + xz[sm2*2+1] + xz[sp4*2+1] + xz[sm4*2+1];
            float* hrow = sm + S_H1 + r * 36;
            const float4* W4 = (const float4*)(sm + S_W1);
            #pragma unroll
            for (int c4 = 0; c4 < 8; c4++) {
                float4 q0 = W4[c4],      q1 = W4[8 + c4],  q2 = W4[16 + c4];
                float4 q3 = W4[24 + c4], q4 = W4[32 + c4], q5 = W4[40 + c4];
                float4 v;
                v.x = to_tf32(fmaxf(a0*q0.x + a1*q1.x + a2*q2.x + a3*q3.x + a4*q4.x + a5*q5.x, 0.f));
                v.y = to_tf32(fmaxf(a0*q0.y + a1*q1.y + a2*q2.y + a3*q3.y + a4*q4.y + a5*q5.y, 0.f));
                v.z = to_tf32(fmaxf(a0*q0.z + a1*q1.z + a2*q2.z + a3*q3.z + a4*q4.z + a5*q5.z, 0.f));
                v.w = to_tf32(fmaxf(a0*q0.w + a1*q1.w + a2*q2.w + a3*q3.w + a4*q4.w + a5*q5.w, 0.f));
                *(float4*)(hrow + c4 * 4) = v;
            }
        }
        __syncthreads();   // (1)

        // ---------------- Phase A2: g[192][68] (12-load scheme) ----------------
        if (tid < 128) {
            const int bt = tid >> 3;     // 0..15
            const int j4 = tid & 7;      // column quad
            const float* hb = sm + S_H1 + bt * 12 * 36 + j4 * 4;
            float4 h[12];
            #pragma unroll
            for (int s = 0; s < 12; s++)
                h[s] = *(const float4*)(hb + s * 36);
            float* gb = sm + S_G + bt * 12 * 68 + j4 * 4;
            #pragma unroll
            for (int s = 0; s < 12; s++) {
                float4 p1 = h[(s+1)%12], m1 = h[(s+11)%12], p3 = h[(s+3)%12], m3 = h[(s+9)%12];
                float4 p2 = h[(s+2)%12], m2 = h[(s+10)%12], p4 = h[(s+4)%12], m4 = h[(s+8)%12];
                float4 g1, g2;
                g1.x = to_tf32(p1.x + m1.x + p3.x + m3.x);
                g1.y = to_tf32(p1.y + m1.y + p3.y + m3.y);
                g1.z = to_tf32(p1.z + m1.z + p3.z + m3.z);
                g1.w = to_tf32(p1.w + m1.w + p3.w + m3.w);
                g2.x = to_tf32(p2.x + m2.x + p4.x + m4.x);
                g2.y = to_tf32(p2.y + m2.y + p4.y + m4.y);
                g2.z = to_tf32(p2.z + m2.z + p4.z + m4.z);
                g2.w = to_tf32(p2.w + m2.w + p4.w + m4.w);
                *(float4*)(gb + s * 68)      = g1;
                *(float4*)(gb + s * 68 + 32) = g2;
            }
        }
        if (zpre) {
            int i = tid / 6, j = tid % 6;
            *(float4*)(zbuf_next + i * 24 + j * 4) = zreg;
        }
        __syncthreads();   // (2)

        // ---------------- Phase B: tf32 mma.sync GEMM (R9 form) ----------------
        // 8 warps: warp = 48 rows x 32 cols (3 m16 x 4 n8 x 12 k-steps)
        float4 w1r[8];
        float4 w2r[4];
        {
            const int mrow = (wid >> 1) * 48;
            const int nb   = (wid & 1) * 32;
            const int gid  = lid >> 2;   // 0..7
            const int tg   = lid & 3;    // 0..3

            float acc[3][4][4];
            #pragma unroll
            for (int mt = 0; mt < 3; mt++)
                #pragma unroll
                for (int nt = 0; nt < 4; nt++)
                    #pragma unroll
                    for (int q = 0; q < 4; q++) acc[mt][nt][q] = 0.f;

            #pragma unroll
            for (int ks = 0; ks < 12; ks++) {
                const float* Bk0 = sm + S_W2 + (ks * 8 + tg) * 72 + nb + gid;
                const float* Bk1 = Bk0 + 4 * 72;
                uint32_t b0[4], b1[4];
                #pragma unroll
                for (int nt = 0; nt < 4; nt++) {
                    b0[nt] = __float_as_uint(Bk0[nt * 8]);
                    b1[nt] = __float_as_uint(Bk1[nt * 8]);
                }
                #pragma unroll
                for (int mt = 0; mt < 3; mt++) {
                    const int r = mrow + mt * 16 + gid;
                    uint32_t a0, a1, a2, a3;
                    if (ks < 4) {
                        const float* Ar  = sm + S_H1 + r * 36 + ks * 8 + tg;
                        const float* Ar8 = Ar + 8 * 36;
                        a0 = __float_as_uint(Ar[0]);
                        a2 = __float_as_uint(Ar[4]);
                        a1 = __float_as_uint(Ar8[0]);
                        a3 = __float_as_uint(Ar8[4]);
                    } else {
                        const float* Ar  = sm + S_G + r * 68 + (ks - 4) * 8 + tg;
                        const float* Ar8 = Ar + 8 * 68;
                        a0 = __float_as_uint(Ar[0]);
                        a2 = __float_as_uint(Ar[4]);
                        a1 = __float_as_uint(Ar8[0]);
                        a3 = __float_as_uint(Ar8[4]);
                    }
                    #pragma unroll
                    for (int nt = 0; nt < 4; nt++)
                        mma_tf32(acc[mt][nt], a0, a1, a2, a3, b0[nt], b1[nt]);
                }
            }
            __syncthreads();   // (3) all reads of h1/g complete

            // store h2 (relu) into g region
            #pragma unroll
            for (int mt = 0; mt < 3; mt++) {
                const int r0 = mrow + mt * 16 + gid;
                #pragma unroll
                for (int nt = 0; nt < 4; nt++) {
                    const int cc = nb + nt * 8 + tg * 2;
                    float2 v0, v1;
                    v0.x = fmaxf(acc[mt][nt][0], 0.f);
                    v0.y = fmaxf(acc[mt][nt][1], 0.f);
                    v1.x = fmaxf(acc[mt][nt][2], 0.f);
                    v1.y = fmaxf(acc[mt][nt][3], 0.f);
                    *(float2*)(sm + S_H2 + r0 * 68 + cc)       = v0;
                    *(float2*)(sm + S_H2 + (r0 + 8) * 68 + cc) = v1;
                }
            }
        }

        // FW1/FW2 global prefetch (acc regs dead; latency hidden by pool)
        #pragma unroll
        for (int j = 0; j < 8; j++) w1r[j] = fw1v[tid + j * NTHREADS];
        #pragma unroll
        for (int j = 0; j < 4; j++) w2r[j] = fw2v[tid + j * NTHREADS];

        __syncthreads();   // (4) h2 visible; h1 fully dead

        // FW2 -> smem (h1 region, disjoint from pool)
        #pragma unroll
        for (int j = 0; j < 4; j++)
            *(float4*)(sm + S_FW2 + (tid + j * NTHREADS) * 4) = w2r[j];

        // ---------------- Pool (vectorized): pooled[16][132] ----------------
        {
            const int bt = tid >> 4;     // 0..15
            const int o4 = tid & 15;     // column quad
            const float* q = sm + S_H2 + bt * 12 * 68 + o4 * 4;
            float4 v = *(const float4*)(q);
            float4 sum = v, mx = v;
            #pragma unroll
            for (int s = 1; s < 12; s++) {
                float4 u = *(const float4*)(q + s * 68);
                sum.x += u.x; sum.y += u.y; sum.z += u.z; sum.w += u.w;
                mx.x = fmaxf(mx.x, u.x); mx.y = fmaxf(mx.y, u.y);
                mx.z = fmaxf(mx.z, u.z); mx.w = fmaxf(mx.w, u.w);
            }
            sum.x *= (1.0f / 12.0f); sum.y *= (1.0f / 12.0f);
            sum.z *= (1.0f / 12.0f); sum.w *= (1.0f / 12.0f);
            *(float4*)(sm + S_POOL + bt * 132 + o4 * 4)      = sum;
            *(float4*)(sm + S_POOL + bt * 132 + 64 + o4 * 4) = mx;
        }
        __syncthreads();   // (5) h2 dead

        // FW1 -> smem (G region)
        #pragma unroll
        for (int j = 0; j < 8; j++)
            *(float4*)(sm + S_FW1 + (tid + j * NTHREADS) * 4) = w1r[j];
        __syncthreads();   // (6) FW1 visible

        // ---------------- fc1 (128->64) + relu: oq = tid>>4, bt = tid&15 ----------------
        {
            const int oq = tid >> 4;     // 0..15
            const int bt = tid & 15;
            float4 b4 = *(const float4*)(sm + S_FB1 + oq * 4);
            unsigned long long acc0 = pk2(b4.x, b4.y);
            unsigned long long acc1 = pk2(b4.z, b4.w);
            const float4* pool4 = (const float4*)(sm + S_POOL + bt * 132);
            #pragma unroll 8
            for (int f4 = 0; f4 < 32; f4++) {
                float4 p4 = pool4[f4];
                #pragma unroll
                for (int kk = 0; kk < 4; kk++) {
                    ulonglong2 w = *(const ulonglong2*)(sm + S_FW1 + (f4 * 4 + kk) * 64 + oq * 4);
                    unsigned long long aa = pk((&p4.x)[kk]);
                    fma2(acc0, aa, w.x);
                    fma2(acc1, aa, w.y);
                }
            }
            float v0, v1, v2, v3;
            unpk(acc0, v0, v1);
            unpk(acc1, v2, v3);
            float4 v;
            v.x = fmaxf(v0, 0.f); v.y = fmaxf(v1, 0.f);
            v.z = fmaxf(v2, 0.f); v.w = fmaxf(v3, 0.f);
            *(float4*)(sm + S_F1 + bt * 68 + oq * 4) = v;
        }
        __syncthreads();   // (7)

        // ---------------- fc2 (64->64) + relu ----------------
        {
            const int oq = tid >> 4;
            const int bt = tid & 15;
            float4 b4 = *(const float4*)(sm + S_FB2 + oq * 4);
            unsigned long long acc0 = pk2(b4.x, b4.y);
            unsigned long long acc1 = pk2(b4.z, b4.w);
            const float4* f1r = (const float4*)(sm + S_F1 + bt * 68);
            #pragma unroll 8
            for (int k4 = 0; k4 < 16; k4++) {
                float4 p4 = f1r[k4];
                #pragma unroll
                for (int kk = 0; kk < 4; kk++) {
                    ulonglong2 w = *(const ulonglong2*)(sm + S_FW2 + (k4 * 4 + kk) * 64 + oq * 4);
                    unsigned long long aa = pk((&p4.x)[kk]);
                    fma2(acc0, aa, w.x);
                    fma2(acc1, aa, w.y);
                }
            }
            float v0, v1, v2, v3;
            unpk(acc0, v0, v1);
            unpk(acc1, v2, v3);
            float4 v;
            v.x = fmaxf(v0, 0.f); v.y = fmaxf(v1, 0.f);
            v.z = fmaxf(v2, 0.f); v.w = fmaxf(v3, 0.f);
            *(float4*)(sm + S_F2 + bt * 68 + oq * 4) = v;
        }
        __syncthreads();   // (8)

        // ---------------- fc3 (64->1) -> out (B, L) ----------------
        if (tid < BT) {
            const float4* f2 = (const float4*)(sm + S_F2 + tid * 68);
            const float4* w3 = (const float4*)(sm + S_FW3);
            float acc = sm[S_FB3];
            #pragma unroll
            for (int k4 = 0; k4 < 16; k4++) {
                float4 a = f2[k4], b = w3[k4];
                acc += a.x * b.x + a.y * b.y + a.z * b.z + a.w * b.w;
            }
            out[(size_t)(b0 + tid) * LAYERS + l] = acc;
        }
        // next phase A writes h1 (POOL/FW2 there dead after fc1/fc2, sync (8));
        // next A2 writes G (FW1/F1/F2 dead: fc3 readers pass sync (1) first).
    }
}

extern "C" void kernel_launch(void* const* d_in, const int* in_sizes, int n_in,
                              void* d_out, int out_size)
{
    (void)in_sizes; (void)n_in; (void)out_size;
    const float* zs  = (const float*)d_in[0];
    const float* w1  = (const float*)d_in[1];
    const float* w2  = (const float*)d_in[2];
    const float* fw1 = (const float*)d_in[3];
    const float* fb1 = (const float*)d_in[4];
    const float* fw2 = (const float*)d_in[5];
    const float* fb2 = (const float*)d_in[6];
    const float* fw3 = (const float*)d_in[7];
    const float* fb3 = (const float*)d_in[8];
    float* out = (float*)d_out;

    static bool attr_set = false;
    if (!attr_set) {
        cudaFuncSetAttribute(twelve_sites_kernel,
                             cudaFuncAttributeMaxDynamicSharedMemorySize,
                             SMEM_BYTES);
        attr_set = true;
    }

    dim3 grid(BATCH / (BT * TILES), LAYERS);   // (16, 63)
    twelve_sites_kernel<<<grid, NTHREADS, SMEM_BYTES>>>(
        zs, w1, w2, fw1, fb1, fw2, fb2, fw3, fb3, out);
}